// round 1
// baseline (speedup 1.0000x reference)
#include <cuda_runtime.h>
#include <math.h>

// Problem constants: B=4, S=2048, E=1024
#define BATCH 4
#define SEQ   2048
#define EMB   1024
#define MTOT  (BATCH * SEQ)   // 8192

// Scratch (device globals: allocation-free per harness rules)
__device__ float g_Q[(long long)BATCH * SEQ * EMB];   // 32 MB
__device__ float g_K[(long long)BATCH * SEQ * EMB];   // 32 MB
__device__ float g_V[(long long)BATCH * SEQ * EMB];   // 32 MB
__device__ float g_S[(long long)BATCH * SEQ * SEQ];   // 64 MB
__device__ float g_O[(long long)BATCH * SEQ * EMB];   // 32 MB

// ---------------------------------------------------------------------------
// Tiled SGEMM: C = alpha * A * op(B) (+ bias)
//   A: [M, K] row-major
//   TRANS_B = true : B is [N, K] row-major (C[m,n] = sum_k A[m,k] * B[n,k])
//   TRANS_B = false: B is [K, N] row-major (C[m,n] = sum_k A[m,k] * B[k,n])
// BM = BN = 128, BK = 16, 256 threads, 8x8 outputs/thread.
// All dims assumed multiples of the tile sizes (true for this problem).
// ---------------------------------------------------------------------------
template <bool TRANS_B, bool ADD_BIAS>
__global__ __launch_bounds__(256, 2)
void sgemm_kernel(const float* __restrict__ A, const float* __restrict__ B,
                  const float* __restrict__ bias, float* __restrict__ C,
                  int M, int N, int K, float alpha,
                  long long strideA, long long strideB, long long strideC)
{
    constexpr int BM = 128, BN = 128, BK = 16;
    __shared__ float As[BK][BM];
    __shared__ float Bs[BK][BN];

    A += (long long)blockIdx.z * strideA;
    B += (long long)blockIdx.z * strideB;
    C += (long long)blockIdx.z * strideC;

    const int m0 = blockIdx.y * BM;
    const int n0 = blockIdx.x * BN;
    const int tid = threadIdx.x;
    const int tx = tid % 16;           // 16 column groups
    const int ty = tid / 16;           // 16 row groups

    float acc[8][8];
    #pragma unroll
    for (int i = 0; i < 8; i++)
        #pragma unroll
        for (int j = 0; j < 8; j++)
            acc[i][j] = 0.0f;

    for (int k0 = 0; k0 < K; k0 += BK) {
        // Load A tile: 128 rows x 16 cols -> As[k][m]
        #pragma unroll
        for (int i = 0; i < 8; i++) {
            int idx = tid + i * 256;           // 0..2047
            int m = idx >> 4;                  // /16
            int k = idx & 15;
            As[k][m] = A[(long long)(m0 + m) * K + (k0 + k)];
        }
        // Load B tile -> Bs[k][n]
        if (TRANS_B) {
            #pragma unroll
            for (int i = 0; i < 8; i++) {
                int idx = tid + i * 256;
                int n = idx >> 4;
                int k = idx & 15;
                Bs[k][n] = B[(long long)(n0 + n) * K + (k0 + k)];
            }
        } else {
            #pragma unroll
            for (int i = 0; i < 8; i++) {
                int idx = tid + i * 256;
                int k = idx >> 7;                // /128
                int n = idx & 127;
                Bs[k][n] = B[(long long)(k0 + k) * N + (n0 + n)];
            }
        }
        __syncthreads();

        #pragma unroll
        for (int k = 0; k < BK; k++) {
            float a[8], b[8];
            // vectorized shared loads
            float4 a0 = *reinterpret_cast<const float4*>(&As[k][ty * 8]);
            float4 a1 = *reinterpret_cast<const float4*>(&As[k][ty * 8 + 4]);
            float4 b0 = *reinterpret_cast<const float4*>(&Bs[k][tx * 8]);
            float4 b1 = *reinterpret_cast<const float4*>(&Bs[k][tx * 8 + 4]);
            a[0]=a0.x; a[1]=a0.y; a[2]=a0.z; a[3]=a0.w;
            a[4]=a1.x; a[5]=a1.y; a[6]=a1.z; a[7]=a1.w;
            b[0]=b0.x; b[1]=b0.y; b[2]=b0.z; b[3]=b0.w;
            b[4]=b1.x; b[5]=b1.y; b[6]=b1.z; b[7]=b1.w;
            #pragma unroll
            for (int i = 0; i < 8; i++)
                #pragma unroll
                for (int j = 0; j < 8; j++)
                    acc[i][j] = fmaf(a[i], b[j], acc[i][j]);
        }
        __syncthreads();
    }

    // Epilogue
    #pragma unroll
    for (int i = 0; i < 8; i++) {
        int m = m0 + ty * 8 + i;
        #pragma unroll
        for (int j = 0; j < 8; j++) {
            int n = n0 + tx * 8 + j;
            float v = acc[i][j] * alpha;
            if (ADD_BIAS) v += bias[n];
            C[(long long)m * N + n] = v;
        }
    }
}

// ---------------------------------------------------------------------------
// Row softmax over 2048-wide rows, one 256-thread block per row.
// ---------------------------------------------------------------------------
__global__ __launch_bounds__(256)
void softmax_kernel(float* __restrict__ S)
{
    const int ncol = SEQ;                   // 2048
    long long base = (long long)blockIdx.x * ncol;
    const int tid = threadIdx.x;
    const int lid = tid & 31;
    const int wid = tid >> 5;

    float v[8];
    float mx = -1e30f;
    #pragma unroll
    for (int i = 0; i < 8; i++) {
        v[i] = S[base + tid + i * 256];
        mx = fmaxf(mx, v[i]);
    }
    #pragma unroll
    for (int o = 16; o > 0; o >>= 1)
        mx = fmaxf(mx, __shfl_xor_sync(0xffffffffu, mx, o));

    __shared__ float smax[8];
    __shared__ float ssum[8];
    if (lid == 0) smax[wid] = mx;
    __syncthreads();
    mx = smax[0];
    #pragma unroll
    for (int w = 1; w < 8; w++) mx = fmaxf(mx, smax[w]);

    float sum = 0.0f;
    #pragma unroll
    for (int i = 0; i < 8; i++) {
        v[i] = __expf(v[i] - mx);
        sum += v[i];
    }
    #pragma unroll
    for (int o = 16; o > 0; o >>= 1)
        sum += __shfl_xor_sync(0xffffffffu, sum, o);
    if (lid == 0) ssum[wid] = sum;
    __syncthreads();
    sum = 0.0f;
    #pragma unroll
    for (int w = 0; w < 8; w++) sum += ssum[w];

    float inv = 1.0f / sum;
    #pragma unroll
    for (int i = 0; i < 8; i++)
        S[base + tid + i * 256] = v[i] * inv;
}

// ---------------------------------------------------------------------------
// Launch
// Inputs (metadata order): x, Wq, bq, Wk, bk, Wv, bv, Wo, bo
// ---------------------------------------------------------------------------
extern "C" void kernel_launch(void* const* d_in, const int* in_sizes, int n_in,
                              void* d_out, int out_size)
{
    const float* x  = (const float*)d_in[0];
    const float* Wq = (const float*)d_in[1];
    const float* bq = (const float*)d_in[2];
    const float* Wk = (const float*)d_in[3];
    const float* bk = (const float*)d_in[4];
    const float* Wv = (const float*)d_in[5];
    const float* bv = (const float*)d_in[6];
    const float* Wo = (const float*)d_in[7];
    const float* bo = (const float*)d_in[8];
    float* out = (float*)d_out;

    float *Q, *K, *V, *S, *O;
    cudaGetSymbolAddress((void**)&Q, g_Q);
    cudaGetSymbolAddress((void**)&K, g_K);
    cudaGetSymbolAddress((void**)&V, g_V);
    cudaGetSymbolAddress((void**)&S, g_S);
    cudaGetSymbolAddress((void**)&O, g_O);

    dim3 blk(256);
    const float scale = 1.0f / 32.0f;   // 1/sqrt(1024)

    // 1) Q/K/V projections: [8192,1024] x [1024,1024]^T + bias (NT)
    dim3 gProj(EMB / 128, MTOT / 128, 1);          // (8, 64)
    sgemm_kernel<true, true><<<gProj, blk>>>(x, Wq, bq, Q, MTOT, EMB, EMB, 1.0f, 0, 0, 0);
    sgemm_kernel<true, true><<<gProj, blk>>>(x, Wk, bk, K, MTOT, EMB, EMB, 1.0f, 0, 0, 0);
    sgemm_kernel<true, true><<<gProj, blk>>>(x, Wv, bv, V, MTOT, EMB, EMB, 1.0f, 0, 0, 0);

    // 2) scores = scale * Q @ K^T, batched over 4 (NT)
    dim3 gScore(SEQ / 128, SEQ / 128, BATCH);      // (16, 16, 4)
    sgemm_kernel<true, false><<<gScore, blk>>>(Q, K, nullptr, S, SEQ, SEQ, EMB, scale,
                                               (long long)SEQ * EMB,
                                               (long long)SEQ * EMB,
                                               (long long)SEQ * SEQ);

    // 3) softmax over rows of S: 4*2048 rows
    softmax_kernel<<<BATCH * SEQ, blk>>>(S);

    // 4) O = P @ V, batched (NN): A=[2048,2048], B=[2048,1024]
    dim3 gOut(EMB / 128, SEQ / 128, BATCH);        // (8, 16, 4)
    sgemm_kernel<false, false><<<gOut, blk>>>(S, V, nullptr, O, SEQ, EMB, SEQ, 1.0f,
                                              (long long)SEQ * SEQ,
                                              (long long)SEQ * EMB,
                                              (long long)SEQ * EMB);

    // 5) final: out = O @ Wo^T + bo (NT), flattened [8192,1024]
    sgemm_kernel<true, true><<<gProj, blk>>>(O, Wo, bo, out, MTOT, EMB, EMB, 1.0f, 0, 0, 0);
}

// round 4
// speedup vs baseline: 3.0996x; 3.0996x over previous
#include <cuda_runtime.h>
#include <cuda_bf16.h>
#include <cstdint>

#define SEQ   2048
#define EMB   1024
#define BATCH 4
#define MTOT  (BATCH * SEQ)   // 8192

// 3-segment split widths
#define K1 (3 * EMB)   // 3072
#define K2 (3 * SEQ)   // 6144

// ---------------- scratch (device globals; allocation-free) ----------------
__device__ __nv_bfloat16 g_xb [(long long)MTOT * K1];     // x  split-A [8192, 3072]
__device__ __nv_bfloat16 g_Wqb[(long long)EMB  * K1];     // weights split-B
__device__ __nv_bfloat16 g_Wkb[(long long)EMB  * K1];
__device__ __nv_bfloat16 g_Wvb[(long long)EMB  * K1];
__device__ __nv_bfloat16 g_Wob[(long long)EMB  * K1];
__device__ __nv_bfloat16 g_Qb [(long long)MTOT * K1];     // split-A
__device__ __nv_bfloat16 g_Kb [(long long)MTOT * K1];     // split-B
__device__ __nv_bfloat16 g_VTb[(long long)BATCH * EMB * K2]; // V^T split-B [b][e][3*SEQ]
__device__ float         g_S  [(long long)BATCH * SEQ * SEQ];
__device__ __nv_bfloat16 g_Pb [(long long)BATCH * SEQ * K2]; // P split-A [b][q][3*SEQ]
__device__ __nv_bfloat16 g_Ob [(long long)MTOT * K1];     // split-A

// ---------------- helpers ----------------
__device__ __forceinline__ uint32_t smem_to_u32(const void* p) {
    uint32_t a;
    asm("{ .reg .u64 t; cvta.to.shared.u64 t, %1; cvt.u32.u64 %0, t; }" : "=r"(a) : "l"(p));
    return a;
}

#define CP_ASYNC16(dst, src) \
    asm volatile("cp.async.cg.shared.global [%0], [%1], 16;" :: "r"(dst), "l"(src))
#define CP_COMMIT() asm volatile("cp.async.commit_group;" ::: "memory")

__device__ __forceinline__ void ldmatrix_x4(uint32_t& r0, uint32_t& r1, uint32_t& r2, uint32_t& r3,
                                            uint32_t addr) {
    asm volatile("ldmatrix.sync.aligned.m8n8.x4.shared.b16 {%0,%1,%2,%3}, [%4];"
                 : "=r"(r0), "=r"(r1), "=r"(r2), "=r"(r3) : "r"(addr));
}

__device__ __forceinline__ void mma16816(float* c, uint32_t a0, uint32_t a1, uint32_t a2, uint32_t a3,
                                         uint32_t b0, uint32_t b1) {
    asm volatile("mma.sync.aligned.m16n8k16.row.col.f32.bf16.bf16.f32 "
                 "{%0,%1,%2,%3}, {%4,%5,%6,%7}, {%8,%9}, {%0,%1,%2,%3};"
                 : "+f"(c[0]), "+f"(c[1]), "+f"(c[2]), "+f"(c[3])
                 : "r"(a0), "r"(a1), "r"(a2), "r"(a3), "r"(b0), "r"(b1));
}

// ---------------- conversion: fp32 -> 3-segment split along K ----------------
// LAYOUT 0 (A): [hi | lo | hi],  LAYOUT 1 (B): [hi | hi | lo]
template <int LAYOUT>
__global__ __launch_bounds__(256)
void cvt_split3(const float* __restrict__ in, __nv_bfloat16* __restrict__ out,
                int C, long long total)
{
    long long idx = (long long)blockIdx.x * blockDim.x + threadIdx.x;
    if (idx >= total) return;
    long long r = idx / C;
    int c = (int)(idx - r * C);
    float x = in[idx];
    __nv_bfloat16 h = __float2bfloat16(x);
    __nv_bfloat16 l = __float2bfloat16(x - __bfloat162float(h));
    long long ro = r * (3LL * C);
    if (LAYOUT == 0) {
        out[ro + c] = h;
        out[ro + C + c] = l;
        out[ro + 2LL * C + c] = h;
    } else {
        out[ro + c] = h;
        out[ro + C + c] = h;
        out[ro + 2LL * C + c] = l;
    }
}

// ---------------- HMMA GEMM: C = alpha * A * B^T (+bias) ----------------
// A [M, Ktot] bf16 row-major, B [N, Ktot] bf16 row-major. Block 128x128, BK=64.
// 256 threads = 8 warps (4M x 2N), warp tile 32x64.
// EPI: 0 = fp32 out
//      1 = split-A bf16 out (row stride 3*Nlog; hi, lo, hi)
//      2 = split-B bf16 out (row stride 3*Nlog; hi, hi, lo)
//      3 = split-B transpose out (V^T: [b][n][3*SEQ]; hi, hi, lo)
#define BK      64
#define NSTAGE  3
#define STAGE_BYTES 32768   // A 16KB + B 16KB
#define GEMM_SMEM (NSTAGE * STAGE_BYTES)

template <int EPI, bool HAS_BIAS>
__global__ __launch_bounds__(256, 2)
void mma_gemm(const __nv_bfloat16* __restrict__ A, const __nv_bfloat16* __restrict__ B,
              const float* __restrict__ bias, void* __restrict__ Out,
              int Nlog, int Ktot, float alpha,
              long long sA, long long sB, long long sO)
{
    extern __shared__ __align__(1024) char smem[];
    const uint32_t smem_base = smem_to_u32(smem);
    const int tid = threadIdx.x;
    const int wid = tid >> 5;
    const int lane = tid & 31;
    const int warp_m = wid & 3;      // 0..3 -> 32-row slab
    const int warp_n = wid >> 2;     // 0..1 -> 64-col slab

    A += (long long)blockIdx.z * sA;
    B += (long long)blockIdx.z * sB;

    const int m0 = blockIdx.y * 128;
    const int n0 = blockIdx.x * 128;

    const int nchunks = Ktot / BK;

    auto load_stage = [&](int chunk, int s) {
        uint32_t sa = smem_base + s * STAGE_BYTES;
        uint32_t sb = sa + 16384;
        long long k0 = (long long)chunk * BK;
        #pragma unroll
        for (int t = 0; t < 4; t++) {
            int idx = tid + t * 256;          // 0..1023
            int r = idx >> 3;                 // row 0..127
            int c = idx & 7;                  // granule 0..7
            uint32_t off = (uint32_t)((r * 8 + (c ^ (r & 7))) * 16);
            CP_ASYNC16(sa + off, (const void*)(A + (long long)(m0 + r) * Ktot + k0 + c * 8));
            CP_ASYNC16(sb + off, (const void*)(B + (long long)(n0 + r) * Ktot + k0 + c * 8));
        }
        CP_COMMIT();
    };

    float acc[2][8][4];
    #pragma unroll
    for (int mi = 0; mi < 2; mi++)
        #pragma unroll
        for (int ni = 0; ni < 8; ni++)
            #pragma unroll
            for (int r = 0; r < 4; r++)
                acc[mi][ni][r] = 0.0f;

    load_stage(0, 0);
    load_stage(1, 1);

    const int a_row = (lane & 15);
    const int a_half = lane >> 4;
    const int b_noff = (lane & 7) + ((lane & 16) ? 8 : 0);
    const int b_kg = (lane & 8) ? 1 : 0;

    for (int i = 0; i < nchunks; i++) {
        if (i + 2 < nchunks) {
            asm volatile("cp.async.wait_group 1;" ::: "memory");
        } else {
            asm volatile("cp.async.wait_group 0;" ::: "memory");
        }
        __syncthreads();

        if (i + 2 < nchunks) load_stage(i + 2, (i + 2) % NSTAGE);

        const int s = i % NSTAGE;
        const uint32_t sa = smem_base + s * STAGE_BYTES;
        const uint32_t sb = sa + 16384;

        #pragma unroll
        for (int kk = 0; kk < 4; kk++) {
            uint32_t af[2][4];
            #pragma unroll
            for (int mi = 0; mi < 2; mi++) {
                int row = warp_m * 32 + mi * 16 + a_row;
                int g = (kk * 2 + a_half) ^ (row & 7);
                ldmatrix_x4(af[mi][0], af[mi][1], af[mi][2], af[mi][3],
                            sa + (uint32_t)((row * 8 + g) * 16));
            }
            uint32_t bf[4][4];
            #pragma unroll
            for (int nt = 0; nt < 4; nt++) {
                int row = warp_n * 64 + nt * 16 + b_noff;
                int g = (kk * 2 + b_kg) ^ (row & 7);
                ldmatrix_x4(bf[nt][0], bf[nt][1], bf[nt][2], bf[nt][3],
                            sb + (uint32_t)((row * 8 + g) * 16));
            }
            #pragma unroll
            for (int mi = 0; mi < 2; mi++)
                #pragma unroll
                for (int ni = 0; ni < 8; ni++) {
                    int nt = ni >> 1;
                    uint32_t b0 = (ni & 1) ? bf[nt][2] : bf[nt][0];
                    uint32_t b1 = (ni & 1) ? bf[nt][3] : bf[nt][1];
                    mma16816(acc[mi][ni], af[mi][0], af[mi][1], af[mi][2], af[mi][3], b0, b1);
                }
        }
        __syncthreads();
    }

    // ---- epilogue ----
    const int rbase = m0 + warp_m * 32 + (lane >> 2);
    const int cbase = n0 + warp_n * 64 + (lane & 3) * 2;

    #pragma unroll
    for (int mi = 0; mi < 2; mi++) {
        #pragma unroll
        for (int ni = 0; ni < 8; ni++) {
            #pragma unroll
            for (int half = 0; half < 2; half++) {
                int gm = rbase + mi * 16 + half * 8;
                int gn = cbase + ni * 8;
                float v0 = acc[mi][ni][half * 2 + 0] * alpha;
                float v1 = acc[mi][ni][half * 2 + 1] * alpha;
                if (HAS_BIAS) { v0 += bias[gn]; v1 += bias[gn + 1]; }
                if (EPI == 0) {
                    float* O = (float*)Out + (long long)blockIdx.z * sO;
                    float2* p = (float2*)&O[(long long)gm * Nlog + gn];
                    *p = make_float2(v0, v1);
                } else if (EPI == 1 || EPI == 2) {
                    __nv_bfloat16* O = (__nv_bfloat16*)Out + (long long)blockIdx.z * sO;
                    long long ro = (long long)gm * (3LL * Nlog);
                    __nv_bfloat16 h0 = __float2bfloat16(v0);
                    __nv_bfloat16 l0 = __float2bfloat16(v0 - __bfloat162float(h0));
                    __nv_bfloat16 h1 = __float2bfloat16(v1);
                    __nv_bfloat16 l1 = __float2bfloat16(v1 - __bfloat162float(h1));
                    if (EPI == 1) {
                        // A-layout: hi, lo, hi
                        *(__nv_bfloat162*)&O[ro + gn] = __nv_bfloat162(h0, h1);
                        *(__nv_bfloat162*)&O[ro + Nlog + gn] = __nv_bfloat162(l0, l1);
                        *(__nv_bfloat162*)&O[ro + 2LL * Nlog + gn] = __nv_bfloat162(h0, h1);
                    } else {
                        // B-layout: hi, hi, lo
                        *(__nv_bfloat162*)&O[ro + gn] = __nv_bfloat162(h0, h1);
                        *(__nv_bfloat162*)&O[ro + Nlog + gn] = __nv_bfloat162(h0, h1);
                        *(__nv_bfloat162*)&O[ro + 2LL * Nlog + gn] = __nv_bfloat162(l0, l1);
                    }
                } else {
                    // V split-B transpose: O[b][n][s]=hi, [SEQ+s]=hi, [2SEQ+s]=lo
                    __nv_bfloat16* O = (__nv_bfloat16*)Out;
                    int b = gm >> 11;
                    int sdx = gm & (SEQ - 1);
                    #pragma unroll
                    for (int e = 0; e < 2; e++) {
                        float v = e ? v1 : v0;
                        int n = gn + e;
                        __nv_bfloat16 h = __float2bfloat16(v);
                        __nv_bfloat16 l = __float2bfloat16(v - __bfloat162float(h));
                        long long base = (long long)b * Nlog * (3LL * SEQ)
                                       + (long long)n * (3LL * SEQ) + sdx;
                        O[base] = h;
                        O[base + SEQ] = h;
                        O[base + 2 * SEQ] = l;
                    }
                }
            }
        }
    }
}

// ---------------- softmax (fp32 in) -> split-A bf16 P ----------------
__global__ __launch_bounds__(256)
void softmax_split(const float* __restrict__ S, __nv_bfloat16* __restrict__ P)
{
    long long row = blockIdx.x;
    const float* in = S + row * SEQ;
    __nv_bfloat16* out = P + row * (3LL * SEQ);
    const int tid = threadIdx.x;
    const int lid = tid & 31;
    const int wid = tid >> 5;

    float v[8];
    float mx = -1e30f;
    #pragma unroll
    for (int i = 0; i < 8; i++) {
        v[i] = in[tid + i * 256];
        mx = fmaxf(mx, v[i]);
    }
    #pragma unroll
    for (int o = 16; o > 0; o >>= 1)
        mx = fmaxf(mx, __shfl_xor_sync(0xffffffffu, mx, o));

    __shared__ float smax[8], ssum[8];
    if (lid == 0) smax[wid] = mx;
    __syncthreads();
    mx = smax[0];
    #pragma unroll
    for (int w = 1; w < 8; w++) mx = fmaxf(mx, smax[w]);

    float sum = 0.0f;
    #pragma unroll
    for (int i = 0; i < 8; i++) {
        v[i] = __expf(v[i] - mx);
        sum += v[i];
    }
    #pragma unroll
    for (int o = 16; o > 0; o >>= 1)
        sum += __shfl_xor_sync(0xffffffffu, sum, o);
    if (lid == 0) ssum[wid] = sum;
    __syncthreads();
    sum = 0.0f;
    #pragma unroll
    for (int w = 0; w < 8; w++) sum += ssum[w];

    float inv = 1.0f / sum;
    #pragma unroll
    for (int i = 0; i < 8; i++) {
        float p = v[i] * inv;
        __nv_bfloat16 h = __float2bfloat16(p);
        __nv_bfloat16 l = __float2bfloat16(p - __bfloat162float(h));
        int col = tid + i * 256;
        out[col] = h;            // hi
        out[SEQ + col] = l;      // lo
        out[2 * SEQ + col] = h;  // hi
    }
}

// ---------------- launch ----------------
extern "C" void kernel_launch(void* const* d_in, const int* in_sizes, int n_in,
                              void* d_out, int out_size)
{
    const float* x  = (const float*)d_in[0];
    const float* Wq = (const float*)d_in[1];
    const float* bq = (const float*)d_in[2];
    const float* Wk = (const float*)d_in[3];
    const float* bk = (const float*)d_in[4];
    const float* Wv = (const float*)d_in[5];
    const float* bv = (const float*)d_in[6];
    const float* Wo = (const float*)d_in[7];
    const float* bo = (const float*)d_in[8];
    float* out = (float*)d_out;

    __nv_bfloat16 *xb, *Wqb, *Wkb, *Wvb, *Wob, *Qb, *Kb, *VTb, *Pb, *Ob;
    float* S;
    cudaGetSymbolAddress((void**)&xb,  g_xb);
    cudaGetSymbolAddress((void**)&Wqb, g_Wqb);
    cudaGetSymbolAddress((void**)&Wkb, g_Wkb);
    cudaGetSymbolAddress((void**)&Wvb, g_Wvb);
    cudaGetSymbolAddress((void**)&Wob, g_Wob);
    cudaGetSymbolAddress((void**)&Qb,  g_Qb);
    cudaGetSymbolAddress((void**)&Kb,  g_Kb);
    cudaGetSymbolAddress((void**)&VTb, g_VTb);
    cudaGetSymbolAddress((void**)&S,   g_S);
    cudaGetSymbolAddress((void**)&Pb,  g_Pb);
    cudaGetSymbolAddress((void**)&Ob,  g_Ob);

    cudaFuncSetAttribute(mma_gemm<0, false>, cudaFuncAttributeMaxDynamicSharedMemorySize, GEMM_SMEM);
    cudaFuncSetAttribute(mma_gemm<0, true >, cudaFuncAttributeMaxDynamicSharedMemorySize, GEMM_SMEM);
    cudaFuncSetAttribute(mma_gemm<1, false>, cudaFuncAttributeMaxDynamicSharedMemorySize, GEMM_SMEM);
    cudaFuncSetAttribute(mma_gemm<1, true >, cudaFuncAttributeMaxDynamicSharedMemorySize, GEMM_SMEM);
    cudaFuncSetAttribute(mma_gemm<2, true >, cudaFuncAttributeMaxDynamicSharedMemorySize, GEMM_SMEM);
    cudaFuncSetAttribute(mma_gemm<3, true >, cudaFuncAttributeMaxDynamicSharedMemorySize, GEMM_SMEM);

    // 1) conversions
    {
        long long tx = (long long)MTOT * EMB;
        cvt_split3<0><<<(unsigned)((tx + 255) / 256), 256>>>(x, xb, EMB, tx);
        long long tw = (long long)EMB * EMB;
        unsigned gw = (unsigned)((tw + 255) / 256);
        cvt_split3<1><<<gw, 256>>>(Wq, Wqb, EMB, tw);
        cvt_split3<1><<<gw, 256>>>(Wk, Wkb, EMB, tw);
        cvt_split3<1><<<gw, 256>>>(Wv, Wvb, EMB, tw);
        cvt_split3<1><<<gw, 256>>>(Wo, Wob, EMB, tw);
    }

    dim3 blk(256);
    const float scale = 1.0f / 32.0f;

    // 2) projections: [8192,3072] x [1024,3072]^T
    dim3 gProj(EMB / 128, MTOT / 128, 1);
    mma_gemm<1, true><<<gProj, blk, GEMM_SMEM>>>(xb, Wqb, bq, Qb, EMB, K1, 1.0f, 0, 0, 0);
    mma_gemm<2, true><<<gProj, blk, GEMM_SMEM>>>(xb, Wkb, bk, Kb, EMB, K1, 1.0f, 0, 0, 0);
    mma_gemm<3, true><<<gProj, blk, GEMM_SMEM>>>(xb, Wvb, bv, VTb, EMB, K1, 1.0f, 0, 0, 0);

    // 3) scores = scale * Q K^T  (fp32 out); Q split-A, K split-B
    dim3 gScore(SEQ / 128, SEQ / 128, BATCH);
    mma_gemm<0, false><<<gScore, blk, GEMM_SMEM>>>(
        Qb, Kb, nullptr, S, SEQ, K1, scale,
        (long long)SEQ * K1, (long long)SEQ * K1, (long long)SEQ * SEQ);

    // 4) softmax -> split-A P
    softmax_split<<<BATCH * SEQ, blk>>>(S, Pb);

    // 5) O = P V : A=Pb [2048,6144] split-A, B=VTb [1024,6144] split-B
    dim3 gPV(EMB / 128, SEQ / 128, BATCH);
    mma_gemm<1, false><<<gPV, blk, GEMM_SMEM>>>(
        Pb, VTb, nullptr, Ob, EMB, K2, 1.0f,
        (long long)SEQ * K2, (long long)EMB * K2, (long long)SEQ * K1);

    // 6) out = O Wo^T + bo (fp32 out); O split-A, Wo split-B
    mma_gemm<0, true><<<gProj, blk, GEMM_SMEM>>>(Ob, Wob, bo, out, EMB, K1, 1.0f, 0, 0, 0);
}